// round 1
// baseline (speedup 1.0000x reference)
#include <cuda_runtime.h>

// Problem constants (from reference)
#define BATCH     16384
#define QSEQ      1204
#define FDIM      7
#define NQUAD     301      // 1204/4
#define NCHUNKS   120
#define NOFF      5
#define WINSZ     10
#define NCAT      600      // 120*5
#define H1DIM     128
#define H2DIM     32
#define ODIM      2

#define M_ROWS    16       // batch rows per CTA
#define NTHREADS  256

// Shared layout (floats):
//   region0 [0, 2560):  stage1 scratch sm_out[1204] ALIASED with (sm_h1[2048] | sm_h2[512])
//   sm_cat  [2560, 2560+9600): cat stored k-major: cat[k*16 + r]
// total = 12160 floats = 48640 bytes (fits static smem; 4 CTAs/SM)
__global__ __launch_bounds__(NTHREADS)
void fused_struct3_kernel(
    const float* __restrict__ x,
    const float* __restrict__ w_step,
    const float* __restrict__ b_step,
    const float* __restrict__ wA,
    const float* __restrict__ bA,
    const float* __restrict__ wB,
    const float* __restrict__ bB,
    const float* __restrict__ wC,
    const float* __restrict__ bC,
    float* __restrict__ out)
{
    __shared__ float smem[12160];
    float* sm_out = smem;            // 1204 used (stage 1 only)
    float* sm_h1  = smem;            // 2048 (stages 2+, aliases sm_out)
    float* sm_h2  = smem + 2048;     // 512
    float* sm_cat = smem + 2560;     // 9600

    const int tid = threadIdx.x;
    const size_t b0 = (size_t)blockIdx.x * M_ROWS;

    // broadcast-load step weights into registers (L1/const-cache hot)
    float ws[FDIM];
#pragma unroll
    for (int f = 0; f < FDIM; ++f) ws[f] = __ldg(&w_step[f]);
    const float bs = __ldg(b_step);

    // ---------------- Stage 1: dot-7 + windowed max pool, per row ----------------
    for (int r = 0; r < M_ROWS; ++r) {
        const float* xrow = x + (b0 + (size_t)r) * (size_t)(QSEQ * FDIM);

        // 4 queries per thread-iteration: 28 contiguous floats = 7 x float4 (16B aligned)
        for (int qd = tid; qd < NQUAD; qd += NTHREADS) {
            const float4* p = (const float4*)(xrow + qd * 28);
            float v[28];
#pragma unroll
            for (int i = 0; i < 7; ++i) {
                float4 t = p[i];
                v[i*4+0] = t.x; v[i*4+1] = t.y; v[i*4+2] = t.z; v[i*4+3] = t.w;
            }
#pragma unroll
            for (int qq = 0; qq < 4; ++qq) {
                float acc = bs;
#pragma unroll
                for (int f = 0; f < FDIM; ++f)
                    acc = fmaf(v[qq*FDIM + f], ws[f], acc);
                sm_out[qd*4 + qq] = acc;
            }
        }
        __syncthreads();

        // pooled[c] = max over window of 10 starting at (c/5)*10 + (c%5)
        for (int c = tid; c < NCAT; c += NTHREADS) {
            const int i = c / NOFF;
            const int o = c - i * NOFF;
            const int s = i * WINSZ + o;
            float m = sm_out[s];
#pragma unroll
            for (int w = 1; w < WINSZ; ++w) m = fmaxf(m, sm_out[s + w]);
            sm_cat[c * M_ROWS + r] = m;   // k-major storage
        }
        __syncthreads();
    }

    // ---------------- Stage 2: h1 = relu(cat @ wA + bA) ----------------
    // thread -> output neuron j = tid&127, 8 rows (r0 .. r0+7)
    {
        const int j  = tid & (H1DIM - 1);
        const int r0 = (tid >> 7) * 8;
        float acc[8];
#pragma unroll
        for (int r = 0; r < 8; ++r) acc[r] = 0.0f;

        const float* wAj = wA + j;
#pragma unroll 4
        for (int k = 0; k < NCAT; ++k) {
            const float wa = __ldg(&wAj[k * H1DIM]);           // coalesced 128B, L1/L2 hot
            const float4 c0 = *(const float4*)&sm_cat[k * M_ROWS + r0];
            const float4 c1 = *(const float4*)&sm_cat[k * M_ROWS + r0 + 4];
            acc[0] = fmaf(c0.x, wa, acc[0]);
            acc[1] = fmaf(c0.y, wa, acc[1]);
            acc[2] = fmaf(c0.z, wa, acc[2]);
            acc[3] = fmaf(c0.w, wa, acc[3]);
            acc[4] = fmaf(c1.x, wa, acc[4]);
            acc[5] = fmaf(c1.y, wa, acc[5]);
            acc[6] = fmaf(c1.z, wa, acc[6]);
            acc[7] = fmaf(c1.w, wa, acc[7]);
        }
        const float bj = __ldg(&bA[j]);
        __syncthreads();   // sm_out region dead; safe to write sm_h1 (aliased)
#pragma unroll
        for (int r = 0; r < 8; ++r)
            sm_h1[j * M_ROWS + (r0 + r)] = fmaxf(acc[r] + bj, 0.0f);
    }
    __syncthreads();

    // ---------------- Stage 3: h2 = relu(h1 @ wB + bB) ----------------
    // warp w handles rows 2w, 2w+1; lane = output m
    {
        const int m  = tid & (H2DIM - 1);
        const int rp = tid >> 5;             // 0..7
        float a0 = 0.0f, a1 = 0.0f;
        const float* wBm = wB + m;
#pragma unroll 4
        for (int j = 0; j < H1DIM; ++j) {
            const float wb = __ldg(&wBm[j * H2DIM]);            // coalesced, L1 hot
            const float2 h = *(const float2*)&sm_h1[j * M_ROWS + rp * 2];  // broadcast
            a0 = fmaf(h.x, wb, a0);
            a1 = fmaf(h.y, wb, a1);
        }
        const float bm = __ldg(&bB[m]);
        sm_h2[(rp * 2 + 0) * H2DIM + m] = fmaxf(a0 + bm, 0.0f);
        sm_h2[(rp * 2 + 1) * H2DIM + m] = fmaxf(a1 + bm, 0.0f);
    }
    __syncthreads();

    // ---------------- Stage 4: out = h2 @ wC + bC ----------------
    if (tid < M_ROWS * ODIM) {
        const int r = tid >> 1;
        const int c = tid & 1;
        float acc = __ldg(&bC[c]);
#pragma unroll
        for (int m = 0; m < H2DIM; ++m)
            acc = fmaf(sm_h2[r * H2DIM + m], __ldg(&wC[m * ODIM + c]), acc);
        out[(b0 + (size_t)r) * ODIM + c] = acc;
    }
}

extern "C" void kernel_launch(void* const* d_in, const int* in_sizes, int n_in,
                              void* d_out, int out_size)
{
    const float* x      = (const float*)d_in[0];
    const float* w_step = (const float*)d_in[1];
    const float* b_step = (const float*)d_in[2];
    const float* wA     = (const float*)d_in[3];
    const float* bA     = (const float*)d_in[4];
    const float* wB     = (const float*)d_in[5];
    const float* bB     = (const float*)d_in[6];
    const float* wC     = (const float*)d_in[7];
    const float* bC     = (const float*)d_in[8];
    float* out          = (float*)d_out;

    const int nblocks = BATCH / M_ROWS;   // 1024
    fused_struct3_kernel<<<nblocks, NTHREADS>>>(
        x, w_step, b_step, wA, bA, wB, bB, wC, bC, out);
}